// round 3
// baseline (speedup 1.0000x reference)
#include <cuda_runtime.h>
#include <cstdint>

// ---------------- problem constants ----------------
#define NQ       512          // batch (queries)
#define NA       100000       // number of stored addresses
#define KDIM     1024
#define CDIM     1024
#define NROWPAD  100096       // NA padded to multiple of 128
#define MTILES   6256         // NROWPAD / 16
#define NCTA     1564         // (NROWPAD/128) * 2 N-passes
#define PAIR_CAP (1u<<20)

// ---------------- device globals (static, no runtime alloc) ----------------
// A fragments: [mtile(6256)][kstep(32)][lane(32)][reg(4)] uint32 words (s8x4)
__device__ unsigned g_afrag[MTILES * 32 * 32 * 4];
// B fragments: [pair(32)][kstep(32)][lane(32)][reg(4)]  (pair = 2 n8-tiles)
__device__ unsigned g_bfrag[32 * 32 * 32 * 4];
__device__ unsigned g_npairs;
__device__ unsigned g_pairs[PAIR_CAP];

// ---------------- IMMA: m16n8k32 s8*s8 -> s32 (plain PTX, sm_80+) ----------------
__device__ __forceinline__ void imma(int* c, const uint4& a, unsigned b0, unsigned b1) {
    asm volatile(
        "mma.sync.aligned.m16n8k32.row.col.s32.s8.s8.s32 "
        "{%0,%1,%2,%3}, {%4,%5,%6,%7}, {%8,%9}, {%0,%1,%2,%3};"
        : "+r"(c[0]), "+r"(c[1]), "+r"(c[2]), "+r"(c[3])
        : "r"(a.x), "r"(a.y), "r"(a.z), "r"(a.w), "r"(b0), "r"(b1));
}

__device__ __forceinline__ unsigned pack4(float a, float b, float c, float d) {
    int x0 = (int)a, x1 = (int)b, x2 = (int)c, x3 = (int)d;
    return (x0 & 0xFF) | ((x1 & 0xFF) << 8) | ((x2 & 0xFF) << 16) | ((x3 & 0xFF) << 24);
}

// ---------------- kernel: convert addresses fp32 -> s8 fragment layout ----------------
// grid = NROWPAD blocks (one address row each), 256 threads (one 4-elem k-word each)
__global__ void conva_kernel(const float* __restrict__ A) {
    const int r = blockIdx.x;        // address row (incl. zero padding rows)
    const int j = threadIdx.x;       // k-word 0..255
    unsigned pk = 0;
    if (r < NA) {
        float4 v = reinterpret_cast<const float4*>(A)[(size_t)r * 256 + j];
        pk = pack4(v.x, v.y, v.z, v.w);
    }
    const int mt = r >> 4, ks = j >> 3, w = j & 7;
    const int lane = ((r & 7) << 2) | (w & 3);
    const int reg  = ((w >> 2) << 1) | ((r & 15) >> 3);
    g_afrag[((((mt * 32) + ks) * 32 + lane) << 2) + reg] = pk;
}

// ---------------- kernel: convert queries fp32 -> s8 fragment layout ----------------
__global__ void convb_kernel(const float* __restrict__ Q) {
    const int r = blockIdx.x;        // query row 0..511
    const int j = threadIdx.x;       // k-word 0..255
    float4 v = reinterpret_cast<const float4*>(Q)[(size_t)r * 256 + j];
    unsigned pk = pack4(v.x, v.y, v.z, v.w);
    const int nt = r >> 3, p = nt >> 1, ks = j >> 3, w = j & 7;
    const int lane = ((r & 7) << 2) | (w & 3);
    const int reg  = ((nt & 1) << 1) | (w >> 2);
    g_bfrag[((((p * 32) + ks) * 32 + lane) << 2) + reg] = pk;
}

// ---------------- kernel: zero output + pair counter ----------------
__global__ void zero_kernel(float* __restrict__ out) {
    int i = blockIdx.x * blockDim.x + threadIdx.x;
    out[i] = 0.0f;
    if (i == 0) g_npairs = 0u;
}

// ---------------- kernel: int8 similarity GEMM + threshold + compaction ----------------
// CTA: 128 M x 256 N. 8 warps = 2(M) x 4(N) of 64x64 warptiles.
// Consecutive CTA pairs share the same A tile (L2 reuse), differ in N-pass.
__global__ __launch_bounds__(256, 1) void gemm_kernel(const int* __restrict__ thrp) {
    const int tid = threadIdx.x, lane = tid & 31, wid = tid >> 5;
    const int cta = blockIdx.x;
    const int mtile_base = (cta >> 1) * 8 + (wid & 1) * 4;   // 4 m16 tiles per warp
    const int pass = cta & 1;
    const int nt_base = pass * 32 + (wid >> 1) * 8;          // 8 n8 tiles per warp
    const int p_base = nt_base >> 1;                          // 4 B-pairs per warp

    int acc[4][8][4];
    #pragma unroll
    for (int mi = 0; mi < 4; mi++)
        #pragma unroll
        for (int ni = 0; ni < 8; ni++)
            #pragma unroll
            for (int rr = 0; rr < 4; rr++) acc[mi][ni][rr] = 0;

    const uint4* __restrict__ ab = reinterpret_cast<const uint4*>(g_afrag);
    const uint4* __restrict__ bb = reinterpret_cast<const uint4*>(g_bfrag);

    uint4 a[4], b[4];
    #pragma unroll
    for (int i = 0; i < 4; i++) a[i] = ab[((mtile_base + i) * 32 + 0) * 32 + lane];
    #pragma unroll
    for (int i = 0; i < 4; i++) b[i] = bb[((p_base + i) * 32 + 0) * 32 + lane];

    #pragma unroll 1
    for (int ks = 0; ks < 32; ks++) {
        uint4 an[4], bn[4];
        const int ksn = (ks < 31) ? ks + 1 : 31;
        #pragma unroll
        for (int i = 0; i < 4; i++) an[i] = ab[((mtile_base + i) * 32 + ksn) * 32 + lane];
        #pragma unroll
        for (int i = 0; i < 4; i++) bn[i] = bb[((p_base + i) * 32 + ksn) * 32 + lane];

        #pragma unroll
        for (int mi = 0; mi < 4; mi++)
            #pragma unroll
            for (int pi = 0; pi < 4; pi++) {
                imma(acc[mi][2 * pi],     a[mi], b[pi].x, b[pi].y);
                imma(acc[mi][2 * pi + 1], a[mi], b[pi].z, b[pi].w);
            }
        #pragma unroll
        for (int i = 0; i < 4; i++) { a[i] = an[i]; b[i] = bn[i]; }
    }

    // threshold: robust to int32 or float32 payload
    int tb = *thrp;
    const int thr = (tb > -1000000 && tb < 1000000) ? tb : (int)__int_as_float(tb);

    // epilogue: c0: row=lane/4, col=(lane%4)*2 ; c1: col+1 ; c2,c3: row+8
    #pragma unroll
    for (int mi = 0; mi < 4; mi++)
        #pragma unroll
        for (int ni = 0; ni < 8; ni++)
            #pragma unroll
            for (int rr = 0; rr < 4; rr++) {
                int v = acc[mi][ni][rr];
                if (v >= thr) {
                    int row = (mtile_base + mi) * 16 + (lane >> 2) + ((rr >> 1) << 3);
                    int q   = (nt_base + ni) * 8 + ((lane & 3) << 1) + (rr & 1);
                    if (row < NA) {
                        unsigned idx = atomicAdd(&g_npairs, 1u);
                        if (idx < PAIR_CAP)
                            g_pairs[idx] = ((unsigned)q << 17) | (unsigned)row;
                    }
                }
            }
}

// ---------------- kernel: scatter content rows of active pairs ----------------
__global__ __launch_bounds__(256) void scatter_kernel(const float* __restrict__ content,
                                                      float* __restrict__ out) {
    unsigned np = g_npairs;
    if (np > PAIR_CAP) np = PAIR_CAP;
    for (unsigned p = blockIdx.x; p < np; p += gridDim.x) {
        unsigned pr = g_pairs[p];
        unsigned q = pr >> 17;
        unsigned n = pr & 0x1FFFFu;
        float4 v = reinterpret_cast<const float4*>(content + (size_t)n * CDIM)[threadIdx.x];
        float* dst = out + (size_t)q * CDIM + threadIdx.x * 4;
        atomicAdd(dst + 0, v.x);
        atomicAdd(dst + 1, v.y);
        atomicAdd(dst + 2, v.z);
        atomicAdd(dst + 3, v.w);
    }
}

// ---------------- kernel: sign in place ----------------
__global__ void sign_kernel(float* __restrict__ out) {
    int i = blockIdx.x * blockDim.x + threadIdx.x;
    float v = out[i];
    out[i] = (v > 0.0f) ? 1.0f : ((v < 0.0f) ? -1.0f : 0.0f);
}

// ---------------- launcher ----------------
extern "C" void kernel_launch(void* const* d_in, const int* in_sizes, int n_in,
                              void* d_out, int out_size) {
    const float* q   = (const float*)d_in[0];   // address    [512,1024]
    const float* A   = (const float*)d_in[1];   // addresses  [100000,1024]
    const float* C   = (const float*)d_in[2];   // content    [100000,1024]
    const int*   thr = (const int*)  d_in[3];   // threshold scalar
    float* out = (float*)d_out;                 // [512,1024] float32

    zero_kernel<<<(NQ * CDIM) / 256, 256>>>(out);
    convb_kernel<<<NQ, 256>>>(q);
    conva_kernel<<<NROWPAD, 256>>>(A);
    gemm_kernel<<<NCTA, 256>>>(thr);
    scatter_kernel<<<2048, 256>>>(C, out);
    sign_kernel<<<(NQ * CDIM) / 256, 256>>>(out);
}